// round 8
// baseline (speedup 1.0000x reference)
#include <cuda_runtime.h>

#define XSIZE 256

// 256 threads/block = 2 patch-rows x 128 cols; 1 patch/thread.
__global__ __launch_bounds__(256, 6) void qconv_kernel6(const float* __restrict__ x,
                                                        const float* __restrict__ w,
                                                        float* __restrict__ out)
{
    __shared__ float sh[5];   // tau0..3, scale
    if (threadIdx.x == 0) {
        float C = 1.0f;
#pragma unroll
        for (int q = 0; q < 4; q++) {
            float cq, sq;
            __sincosf(0.5f * __ldg(w + q), &sq, &cq);
            sh[q] = __fdividef(sq, cq);     // tan(w_q/2)
            C *= cq;
        }
        sh[4] = 0.0625f * C * C;            // fold prod cos^2 into prob scale
    }
    __syncthreads();

    const int col  = threadIdx.x & 127;
    const int prow = threadIdx.x >> 7;
    const int b    = blockIdx.x >> 6;
    const int i    = ((blockIdx.x & 63) << 1) | prow;   // patch row 0..127
    const size_t base = ((size_t)b * XSIZE + 2 * i) * XSIZE + 2 * col;
    const float2 r0 = *reinterpret_cast<const float2*>(x + base);
    const float2 r1 = *reinterpret_cast<const float2*>(x + base + XSIZE);
    const float x0 = r0.x, x1 = r0.y, x2 = r1.x, x3 = r1.y;

    // t_e = x3 +- x2 +- x1 +- x0 (bit2->x2, bit1->x1, bit0->x0), parallel form
    const float ap = x3 + x2, am = x3 - x2;
    const float bp = x1 + x0, bm = x1 - x0;
    float t[8];
    t[0] = am - bp;  t[1] = am - bm;  t[2] = am + bm;  t[3] = am + bp;
    t[4] = ap - bp;  t[5] = ap - bm;  t[6] = ap + bm;  t[7] = ap + bp;

    // Phases with the common S/4 term dropped (global phase):
    //   phi(8|e)  = -h^2 - h,  phi(e^7) = -h^2 + h,  h = t_e/2
    float vr[16], vi[16];
#pragma unroll
    for (int e = 0; e < 8; e++) {
        const float h  = 0.5f * t[e];
        const float p1 = __fmaf_rn(-h, h, -h);
        const float p0 = __fmaf_rn(-h, h,  h);
        __sincosf(p1, &vi[8 | e], &vr[8 | e]);
        __sincosf(p0, &vi[e ^ 7], &vr[e ^ 7]);
    }

    const float tau[4] = {sh[0], sh[1], sh[2], sh[3]};
    const float scale  = sh[4];

    // RX butterflies, tangent form (4 fma each); cos factors folded into scale.
#pragma unroll
    for (int q = 0; q < 4; q++) {
        const float tq = tau[q];
#pragma unroll
        for (int m = 0; m < 8; m++) {
            const int j0 = ((m >> q) << (q + 1)) | (m & ((1 << q) - 1));
            const int j1 = j0 | (1 << q);
            const float ar = vr[j0], ai = vi[j0];
            const float br = vr[j1], bim = vi[j1];
            vr[j0] = __fmaf_rn( tq, bim, ar);
            vi[j0] = __fmaf_rn(-tq, br,  ai);
            vr[j1] = __fmaf_rn( tq, ai,  br);
            vi[j1] = __fmaf_rn(-tq, ar,  bim);
        }
    }

    // CNOT ring + per-qubit Z readout = parity-masked probability sums.
    float o0 = 0.f, o1 = 0.f, o2 = 0.f, o3 = 0.f;
#pragma unroll
    for (int k = 0; k < 16; k++) {
        const float p = __fmaf_rn(vr[k], vr[k], vi[k] * vi[k]);
        if (__popc(k & 0xF) & 1) o0 += p;
        if (__popc(k & 0x7) & 1) o1 += p;
        if (__popc(k & 0x3) & 1) o2 += p;
        if (__popc(k & 0xE) & 1) o3 += p;
    }

    float4 o;
    o.x = scale * o0;
    o.y = scale * o1;
    o.z = scale * o2;
    o.w = scale * o3;
    reinterpret_cast<float4*>(out)[((size_t)b * 128 + i) * 128 + col] = o;
}

extern "C" void kernel_launch(void* const* d_in, const int* in_sizes, int n_in,
                              void* d_out, int out_size)
{
    const float* x = (const float*)d_in[0];
    const float* w = (const float*)d_in[1];
    float* out = (float*)d_out;
    const int batch = in_sizes[0] / (XSIZE * XSIZE);
    qconv_kernel6<<<batch * 64, 256>>>(x, w, out);
}

// round 9
// speedup vs baseline: 1.1236x; 1.1236x over previous
#include <cuda_runtime.h>

#define XSIZE 256

// phase prep: t_e = x3 ± x2 ± x1 ± x0 (bit2->x2, bit1->x1, bit0->x0)
#define PREP(T, X0, X1, X2, X3)                                   \
    {                                                             \
        const float ap = (X3) + (X2), am = (X3) - (X2);           \
        const float bp = (X1) + (X0), bm = (X1) - (X0);           \
        T[0] = am - bp; T[1] = am - bm; T[2] = am + bm; T[3] = am + bp; \
        T[4] = ap - bp; T[5] = ap - bm; T[6] = ap + bm; T[7] = ap + bp; \
    }

// diag pair (8|e, e^7): phi = -h^2 ∓ h, h = t_e/2 (global S/4 phase dropped)
#define EMIT(VR, VI, T, E)                                        \
    {                                                             \
        const float h  = 0.5f * T[E];                             \
        const float p1 = __fmaf_rn(-h, h, -h);                    \
        const float p0 = __fmaf_rn(-h, h,  h);                    \
        __sincosf(p1, &VI[8 | (E)], &VR[8 | (E)]);                \
        __sincosf(p0, &VI[(E) ^ 7], &VR[(E) ^ 7]);                \
    }

// one tangent-form RX butterfly on (j0, j1) with tau tq
#define BF(VR, VI, Q, M, TQ)                                      \
    {                                                             \
        const int j0 = (((M) >> (Q)) << ((Q) + 1)) | ((M) & ((1 << (Q)) - 1)); \
        const int j1 = j0 | (1 << (Q));                           \
        const float ar = VR[j0], ai = VI[j0];                     \
        const float br = VR[j1], bim = VI[j1];                    \
        VR[j0] = __fmaf_rn( (TQ), bim, ar);                       \
        VI[j0] = __fmaf_rn(-(TQ), br,  ai);                       \
        VR[j1] = __fmaf_rn( (TQ), ai,  br);                       \
        VI[j1] = __fmaf_rn(-(TQ), ar,  bim);                      \
    }

#define LAYER_HALF(VR, VI, Q, MBASE, TQ)                          \
    BF(VR, VI, Q, (MBASE) + 0, TQ) BF(VR, VI, Q, (MBASE) + 1, TQ) \
    BF(VR, VI, Q, (MBASE) + 2, TQ) BF(VR, VI, Q, (MBASE) + 3, TQ)

// CNOT ring + per-qubit Z readout = parity-masked probability sums
#define READOUT(VR, VI, O, SC)                                    \
    {                                                             \
        float o0 = 0.f, o1 = 0.f, o2 = 0.f, o3 = 0.f;             \
        _Pragma("unroll")                                         \
        for (int k = 0; k < 16; k++) {                            \
            const float p = __fmaf_rn(VR[k], VR[k], VI[k] * VI[k]); \
            if (__popc(k & 0xF) & 1) o0 += p;                     \
            if (__popc(k & 0x7) & 1) o1 += p;                     \
            if (__popc(k & 0x3) & 1) o2 += p;                     \
            if (__popc(k & 0xE) & 1) o3 += p;                     \
        }                                                         \
        O.x = (SC) * o0; O.y = (SC) * o1;                         \
        O.z = (SC) * o2; O.w = (SC) * o3;                         \
    }

// 64 threads/block; each thread software-pipelines TWO adjacent patches so the
// sincos (MUFU) burst of patch B overlaps the butterfly (FMA) burst of patch A.
__global__ __launch_bounds__(64) void qconv_kernel7(const float* __restrict__ x,
                                                    const float* __restrict__ w,
                                                    float* __restrict__ out)
{
    __shared__ float sh[5];   // tau0..3, scale
    if (threadIdx.x == 0) {
        float C = 1.0f;
#pragma unroll
        for (int q = 0; q < 4; q++) {
            float cq, sq;
            __sincosf(0.5f * __ldg(w + q), &sq, &cq);
            sh[q] = __fdividef(sq, cq);     // tan(w_q/2)
            C *= cq;
        }
        sh[4] = 0.0625f * C * C;            // prod cos^2 folded into prob scale
    }
    __syncthreads();
    const float u0 = sh[0], u1 = sh[1], u2 = sh[2], u3 = sh[3];
    const float scale = sh[4];

    const int t  = threadIdx.x;          // 0..63 -> patch pair
    const int bi = blockIdx.x;           // b*128 + i
    const int i  = bi & 127;
    const size_t base = ((size_t)(bi >> 7) * XSIZE + 2 * i) * XSIZE + 4 * t;
    const float4 r0 = *reinterpret_cast<const float4*>(x + base);
    const float4 r1 = *reinterpret_cast<const float4*>(x + base + XSIZE);

    float tA[8], tB[8];
    PREP(tA, r0.x, r0.y, r1.x, r1.y);
    PREP(tB, r0.z, r0.w, r1.z, r1.w);

    float vrA[16], viA[16], vrB[16], viB[16];

    // ── window 1: phases of A (pure MUFU)
    EMIT(vrA, viA, tA, 0) EMIT(vrA, viA, tA, 1)
    EMIT(vrA, viA, tA, 2) EMIT(vrA, viA, tA, 3)
    EMIT(vrA, viA, tA, 4) EMIT(vrA, viA, tA, 5)
    EMIT(vrA, viA, tA, 6) EMIT(vrA, viA, tA, 7)

    // ── window 2: phases of B interleaved with butterflies of A (MUFU ∥ FMA)
    EMIT(vrB, viB, tB, 0) BF(vrA, viA, 0, 0, u0) BF(vrA, viA, 0, 1, u0)
    EMIT(vrB, viB, tB, 1) BF(vrA, viA, 0, 2, u0) BF(vrA, viA, 0, 3, u0)
    EMIT(vrB, viB, tB, 2) BF(vrA, viA, 0, 4, u0) BF(vrA, viA, 0, 5, u0)
    EMIT(vrB, viB, tB, 3) BF(vrA, viA, 0, 6, u0) BF(vrA, viA, 0, 7, u0)
    EMIT(vrB, viB, tB, 4) LAYER_HALF(vrA, viA, 1, 0, u1)
    EMIT(vrB, viB, tB, 5) LAYER_HALF(vrA, viA, 1, 4, u1)
    EMIT(vrB, viB, tB, 6) LAYER_HALF(vrA, viA, 2, 0, u2)
    EMIT(vrB, viB, tB, 7) LAYER_HALF(vrA, viA, 2, 4, u2)

    // ── window 3: finish A, then all-FMA work of B
    LAYER_HALF(vrA, viA, 3, 0, u3)
    LAYER_HALF(vrA, viA, 3, 4, u3)

    float4 oa, ob;
    READOUT(vrA, viA, oa, scale)

    LAYER_HALF(vrB, viB, 0, 0, u0)
    LAYER_HALF(vrB, viB, 0, 4, u0)
    LAYER_HALF(vrB, viB, 1, 0, u1)
    LAYER_HALF(vrB, viB, 1, 4, u1)
    LAYER_HALF(vrB, viB, 2, 0, u2)
    LAYER_HALF(vrB, viB, 2, 4, u2)
    LAYER_HALF(vrB, viB, 3, 0, u3)
    LAYER_HALF(vrB, viB, 3, 4, u3)
    READOUT(vrB, viB, ob, scale)

    float* dst = out + (size_t)bi * 512 + 8 * t;
    reinterpret_cast<float4*>(dst)[0] = oa;
    reinterpret_cast<float4*>(dst)[1] = ob;
}

extern "C" void kernel_launch(void* const* d_in, const int* in_sizes, int n_in,
                              void* d_out, int out_size)
{
    const float* x = (const float*)d_in[0];
    const float* w = (const float*)d_in[1];
    float* out = (float*)d_out;
    const int batch = in_sizes[0] / (XSIZE * XSIZE);
    qconv_kernel7<<<batch * 128, 64>>>(x, w, out);
}